// round 1
// baseline (speedup 1.0000x reference)
#include <cuda_runtime.h>
#include <cstdint>

// GlobalShift2dV2Portion: (16, 512, 64, 64) fp32.
// Channels [0,256): identity. Channels [256,512): per channel-group g=(c-256)>>4,
// the 16 spatial 16x16 blocks (t = a*4+e) are cyclically rotated:
//   out block t' reads input block t = (g + t') & 15.
// Pure permutation -> memory-bound gather with linear writes, 64B-contiguous reads.

__global__ void __launch_bounds__(256) shift_perm_kernel(
    const float4* __restrict__ in, float4* __restrict__ out)
{
    unsigned i = blockIdx.x * 256u + threadIdx.x;   // float4 index, [0, 2^23)

    // Decompose: per (b,c) plane = 64 rows * 16 float4 = 1024 float4 = 2^10
    unsigned w4 = i & 15u;           // float4 within 64-float row
    unsigned h  = (i >> 4) & 63u;
    unsigned c  = (i >> 10) & 511u;
    unsigned b  = i >> 19;

    unsigned src = i;
    if (c >= 256u) {
        unsigned cp  = c - 256u;
        unsigned g   = cp >> 4;          // channel group within shifted slab
        unsigned ap  = h >> 4;           // output spatial block row
        unsigned hh  = h & 15u;
        unsigned ep  = w4 >> 2;          // output spatial block col (w4*4 floats / 16)
        unsigned ww4 = w4 & 3u;          // float4 within 16-float block
        unsigned t   = (g + ap * 4u + ep) & 15u;   // input block index
        unsigned a   = t >> 2;
        unsigned e   = t & 3u;
        src = ((b << 9) + c) * 1024u + ((a * 16u + hh) << 4) + (e * 4u + ww4);
    }
    out[i] = __ldg(in + src);
}

extern "C" void kernel_launch(void* const* d_in, const int* in_sizes, int n_in,
                              void* d_out, int out_size)
{
    const float4* in  = (const float4*)d_in[0];
    float4*       out = (float4*)d_out;
    unsigned n4 = (unsigned)(out_size / 4);         // 8,388,608
    unsigned blocks = (n4 + 255u) / 256u;           // 32,768
    shift_perm_kernel<<<blocks, 256>>>(in, out);
}

// round 2
// speedup vs baseline: 1.0426x; 1.0426x over previous
#include <cuda_runtime.h>
#include <cstdint>

// GlobalShift2dV2Portion: (16, 512, 64, 64) fp32.
// Channels [0,256): identity. Channels [256,512): per channel-group g=(c-256)>>4,
// the 16 spatial 16x16 blocks (t = a*4+e) are cyclically rotated:
//   out block t' reads input block t = (g + t') & 15.
// Pure streaming permutation. R2: 4 independent float4 per thread (MLP batching),
// evict-first load/store hints (zero reuse; don't pollute L2).

static __device__ __forceinline__ unsigned src_of(unsigned i)
{
    unsigned w4 = i & 15u;           // float4 within 64-float row
    unsigned h  = (i >> 4) & 63u;
    unsigned c  = (i >> 10) & 511u;

    if (c < 256u) return i;

    unsigned b   = i >> 19;
    unsigned g   = (c - 256u) >> 4;  // channel group within shifted slab
    unsigned ap  = h >> 4;           // output spatial block row
    unsigned hh  = h & 15u;
    unsigned ep  = w4 >> 2;          // output spatial block col
    unsigned ww4 = w4 & 3u;          // float4 within 16-float block
    unsigned t   = (g + ap * 4u + ep) & 15u;   // input block index
    unsigned a   = t >> 2;
    unsigned e   = t & 3u;
    return ((b << 9) + c) * 1024u + ((a * 16u + hh) << 4) + (e * 4u + ww4);
}

__global__ void __launch_bounds__(256) shift_perm_kernel(
    const float4* __restrict__ in, float4* __restrict__ out)
{
    const unsigned STRIDE = 1u << 21;               // n4 / 4
    unsigned i0 = blockIdx.x * 256u + threadIdx.x;  // [0, 2^21)
    unsigned i1 = i0 + STRIDE;
    unsigned i2 = i0 + 2u * STRIDE;
    unsigned i3 = i0 + 3u * STRIDE;

    // Front-batch 4 independent gathers (MLP=4), streaming policy.
    float4 v0 = __ldcs(in + src_of(i0));
    float4 v1 = __ldcs(in + src_of(i1));
    float4 v2 = __ldcs(in + src_of(i2));
    float4 v3 = __ldcs(in + src_of(i3));

    __stcs(out + i0, v0);
    __stcs(out + i1, v1);
    __stcs(out + i2, v2);
    __stcs(out + i3, v3);
}

extern "C" void kernel_launch(void* const* d_in, const int* in_sizes, int n_in,
                              void* d_out, int out_size)
{
    const float4* in  = (const float4*)d_in[0];
    float4*       out = (float4*)d_out;
    // n4 = 2^23 float4 total; 4 per thread -> 2^21 threads -> 8192 blocks of 256
    shift_perm_kernel<<<8192, 256>>>(in, out);
}